// round 10
// baseline (speedup 1.0000x reference)
#include <cuda_runtime.h>
#include <cuda_fp16.h>
#include <stdint.h>

// ===================================================================
// Fused int8-dequant linear (sm_103 base ISA: no tcgen05).
//   out[m][n] = f32( f16( sum_k f16(x[m][k]) * (f16(wq[n][k])*f16(scale[n])) ) + f16(bias[n]) )
// Harness dtypes: x f32, weight_q i32, scale f32, bias f32, out f32.
// M=2048, N=11008, K=4096.
//
// Stage 1: prep kernels dequant W -> f16 / convert x -> f16 into scratch,
//   16KB SW128-swizzled tiles [128 rows x 64 halves].
// Stage 2: GEMM, CTA 128x128, BK=64, 3-stage cp.async.bulk ring,
//   4 compute warps (2x2, 64x64) + 1 producer, 2 CTAs/SM.
//   Fragment DOUBLE BUFFERING: LDSM for step i+1 issued under the
//   32-HMMA burst of step i; early empty-arrive after last stage read;
//   next-stage ks0 frags peek-loaded under the final burst.
// ===================================================================

#define NTILE_MAX 86
#define MTILE_MAX 16
#define KTILES_MAX 64

__device__ __half g_wf16[(size_t)NTILE_MAX * KTILES_MAX * 8192];
__device__ __half g_xf16[(size_t)MTILE_MAX * KTILES_MAX * 8192];

// ------------------------- PTX helpers -----------------------------
__device__ __forceinline__ uint32_t smem_u32(const void* p) {
    uint32_t a;
    asm("{ .reg .u64 t; cvta.to.shared.u64 t, %1; cvt.u32.u64 %0, t; }" : "=r"(a) : "l"(p));
    return a;
}

#define MBAR_INIT(addr, cnt) \
    asm volatile("mbarrier.init.shared.b64 [%0], %1;" :: "r"(addr), "r"(cnt) : "memory")

#define MBAR_EXPECT_TX(addr, bytes) \
    asm volatile("mbarrier.arrive.expect_tx.shared.b64 _, [%0], %1;" :: "r"(addr), "r"(bytes) : "memory")

#define MBAR_ARRIVE(addr) \
    asm volatile("mbarrier.arrive.release.cta.shared.b64 _, [%0];" :: "r"(addr) : "memory")

#define MBAR_WAIT(addr, ph) do {                                            \
    uint32_t _mb = (addr); uint32_t _p = (ph); uint32_t _done;              \
    asm volatile("{\n\t.reg .pred p;\n\t"                                   \
        "mbarrier.try_wait.parity.acquire.cta.shared::cta.b64 p, [%1], %2;\n\t" \
        "selp.b32 %0, 1, 0, p;\n\t}"                                        \
        : "=r"(_done) : "r"(_mb), "r"(_p) : "memory");                      \
    if (!_done) {                                                           \
        asm volatile("{\n\t.reg .pred P1;\n\t"                              \
            "WL_%=:\n\t"                                                    \
            "mbarrier.try_wait.parity.acquire.cta.shared::cta.b64 P1, [%0], %1, 0x989680;\n\t" \
            "@P1 bra.uni WD_%=;\n\t"                                        \
            "bra.uni WL_%=;\n\t"                                            \
            "WD_%=:\n\t}" :: "r"(_mb), "r"(_p) : "memory");                 \
    }                                                                       \
} while (0)

__device__ __forceinline__ void bulk_g2s(uint32_t dst, const void* src, uint32_t bytes, uint32_t mbar) {
    asm volatile(
        "cp.async.bulk.shared::cta.global.mbarrier::complete_tx::bytes [%0], [%1], %2, [%3];"
        :: "r"(dst), "l"(src), "r"(bytes), "r"(mbar) : "memory");
}

__device__ __forceinline__ void ldsm_x4(uint32_t r[4], uint32_t addr) {
    asm volatile("ldmatrix.sync.aligned.m8n8.x4.shared.b16 {%0,%1,%2,%3}, [%4];"
        : "=r"(r[0]), "=r"(r[1]), "=r"(r[2]), "=r"(r[3]) : "r"(addr));
}

__device__ __forceinline__ void mma16816(float d[4], const uint32_t a[4], const uint32_t b[2]) {
    asm volatile(
        "mma.sync.aligned.m16n8k16.row.col.f32.f16.f16.f32 "
        "{%0,%1,%2,%3}, {%4,%5,%6,%7}, {%8,%9}, {%0,%1,%2,%3};\n"
        : "+f"(d[0]), "+f"(d[1]), "+f"(d[2]), "+f"(d[3])
        : "r"(a[0]), "r"(a[1]), "r"(a[2]), "r"(a[3]), "r"(b[0]), "r"(b[1]));
}

__device__ __forceinline__ uint32_t sw128(uint32_t byte_off) {
    return byte_off ^ ((byte_off >> 3) & 0x70);
}

// ------------------------- prep kernels ----------------------------
__global__ __launch_bounds__(256)
void prep_w(const int* __restrict__ wq, const float* __restrict__ scale,
            int K, long total_groups)
{
    long idx = (long)blockIdx.x * blockDim.x + threadIdx.x;
    if (idx >= total_groups) return;
    int grp = (int)(idx & 1023);
    long blk = idx >> 10;
    int ktiles = K >> 6;
    int k_tile = (int)(blk % ktiles);
    int n_tile = (int)(blk / ktiles);
    int r  = grp >> 3;
    int c8 = grp & 7;
    int n = n_tile * 128 + r;
    int k = k_tile * 64 + c8 * 8;

    const int4* p = (const int4*)(wq + (size_t)n * K + k);
    int4 w0 = p[0], w1 = p[1];
    __half s = __float2half_rn(scale[n]);
    __half h[8];
    h[0] = __hmul(__int2half_rn(w0.x), s);
    h[1] = __hmul(__int2half_rn(w0.y), s);
    h[2] = __hmul(__int2half_rn(w0.z), s);
    h[3] = __hmul(__int2half_rn(w0.w), s);
    h[4] = __hmul(__int2half_rn(w1.x), s);
    h[5] = __hmul(__int2half_rn(w1.y), s);
    h[6] = __hmul(__int2half_rn(w1.z), s);
    h[7] = __hmul(__int2half_rn(w1.w), s);

    uint32_t off = sw128((uint32_t)(r * 128 + c8 * 16));
    *(uint4*)((char*)g_wf16 + blk * 16384 + off) = *(uint4*)h;
}

__global__ __launch_bounds__(256)
void prep_x(const float* __restrict__ x, int K, long total_groups)
{
    long idx = (long)blockIdx.x * blockDim.x + threadIdx.x;
    if (idx >= total_groups) return;
    int grp = (int)(idx & 1023);
    long blk = idx >> 10;
    int ktiles = K >> 6;
    int k_tile = (int)(blk % ktiles);
    int m_tile = (int)(blk / ktiles);
    int r  = grp >> 3;
    int c8 = grp & 7;
    int m = m_tile * 128 + r;
    int k = k_tile * 64 + c8 * 8;

    const float4* p = (const float4*)(x + (size_t)m * K + k);
    float4 f0 = p[0], f1 = p[1];
    __half h[8];
    h[0] = __float2half_rn(f0.x); h[1] = __float2half_rn(f0.y);
    h[2] = __float2half_rn(f0.z); h[3] = __float2half_rn(f0.w);
    h[4] = __float2half_rn(f1.x); h[5] = __float2half_rn(f1.y);
    h[6] = __float2half_rn(f1.z); h[7] = __float2half_rn(f1.w);

    uint32_t off = sw128((uint32_t)(r * 128 + c8 * 16));
    *(uint4*)((char*)g_xf16 + blk * 16384 + off) = *(uint4*)h;
}

// ------------------------- GEMM kernel -----------------------------
#define NSTAGES 3
#define TILE_B 16384
#define STAGE_BYTES (2 * TILE_B)
#define CTRL 1024
#define GEMM_SMEM (CTRL + NSTAGES * STAGE_BYTES)   // 99328 -> 2 CTAs/SM
#define NTHREADS_G 160                 // 5 warps

__global__ __launch_bounds__(NTHREADS_G, 2)
void qgemm(const float* __restrict__ bias, float* __restrict__ out,
           int M, int N, int K)
{
    extern __shared__ __align__(1024) char smem[];
    const uint32_t sb = smem_u32(smem);
    const int tid  = threadIdx.x;
    const int lid  = tid & 31;
    const int warp = tid >> 5;

    const int mt_idx = blockIdx.x;         // M tile (fastest -> W L2 reuse)
    const int nt_idx = blockIdx.y;         // N tile
    const int ktiles = K >> 6;
    const int m0 = mt_idx * 128;
    const int n0 = nt_idx * 128;

    if (tid == 0) {
        for (int s = 0; s < NSTAGES; s++) {
            MBAR_INIT(sb + s * 8, 1);            // full
            MBAR_INIT(sb + 32 + s * 8, 4);       // empty
        }
    }
    __syncthreads();

    // ---------------- producer warp ----------------
    if (warp == 4) {
        if (lid == 0) {
            const char* Ag = (const char*)g_xf16 + (size_t)mt_idx * ktiles * TILE_B;
            const char* Bg = (const char*)g_wf16 + (size_t)nt_idx * ktiles * TILE_B;
            int st = 0, php = 1;
            for (int j = 0; j < ktiles; j++) {
                MBAR_WAIT(sb + 32 + st * 8, php);
                const uint32_t mbar = sb + st * 8;
                const uint32_t dst  = sb + CTRL + st * STAGE_BYTES;
                MBAR_EXPECT_TX(mbar, STAGE_BYTES);
                bulk_g2s(dst,          Ag + (size_t)j * TILE_B, TILE_B, mbar);
                bulk_g2s(dst + TILE_B, Bg + (size_t)j * TILE_B, TILE_B, mbar);
                if (++st == NSTAGES) { st = 0; php ^= 1; }
            }
        }
        return;
    }

    // ---------------- compute warps (2x2, warp tile 64x64) ----------------
    const int wm = (warp >> 1) * 64;
    const int wn = (warp & 1) * 64;

    const int ra       = lid & 15;
    const uint32_t swa = (uint32_t)(ra & 7) << 4;
    const uint32_t csa = (uint32_t)(lid >> 4) << 4;
    const int rb       = (lid & 7) + ((lid >> 4) << 3);
    const uint32_t swb = (uint32_t)(rb & 7) << 4;
    const uint32_t csb = (uint32_t)((lid >> 3) & 1) << 4;

    float acc[4][8][4];
#pragma unroll
    for (int i = 0; i < 4; i++)
#pragma unroll
        for (int j = 0; j < 8; j++)
#pragma unroll
            for (int c = 0; c < 4; c++) acc[i][j][c] = 0.f;

    // two fragment buffers
    uint32_t fa0[4][4], fb0[8][2];
    uint32_t fa1[4][4], fb1[8][2];

#define LOADF(FA, FB, ABASE, BBASE, KB) do {                                  \
    _Pragma("unroll")                                                         \
    for (int _mt = 0; _mt < 4; _mt++) {                                       \
        const int _r = wm + _mt * 16 + ra;                                    \
        ldsm_x4(FA[_mt], (ABASE) + (uint32_t)_r * 128 + (((KB) + csa) ^ swa));\
    }                                                                         \
    _Pragma("unroll")                                                         \
    for (int _q = 0; _q < 4; _q++) {                                          \
        const int _n = wn + _q * 16 + rb;                                     \
        uint32_t _t[4];                                                       \
        ldsm_x4(_t, (BBASE) + (uint32_t)_n * 128 + (((KB) + csb) ^ swb));     \
        FB[2*_q][0] = _t[0]; FB[2*_q][1] = _t[1];                             \
        FB[2*_q+1][0] = _t[2]; FB[2*_q+1][1] = _t[3];                         \
    }                                                                         \
} while (0)

#define MMAF(FA, FB) do {                                                     \
    _Pragma("unroll")                                                         \
    for (int _mt = 0; _mt < 4; _mt++)                                         \
        _Pragma("unroll")                                                     \
        for (int _nt = 0; _nt < 8; _nt++)                                     \
            mma16816(acc[_mt][_nt], FA[_mt], FB[_nt]);                        \
} while (0)

    int st = 0, ph = 0;
    // prologue: wait stage 0, load ks0 into buf0
    MBAR_WAIT(sb + 0, 0);
    {
        const uint32_t Ab = sb + CTRL;
        const uint32_t Bb = Ab + TILE_B;
        LOADF(fa0, fb0, Ab, Bb, 0u);
    }

    for (int kt = 0; kt < ktiles; kt++) {
        const uint32_t Abase = sb + CTRL + st * STAGE_BYTES;
        const uint32_t Bbase = Abase + TILE_B;
        const int stn = (st + 1 == NSTAGES) ? 0 : st + 1;
        const int phn = (st + 1 == NSTAGES) ? (ph ^ 1) : ph;

        // ks0: load ks1 -> buf1, mma buf0
        LOADF(fa1, fb1, Abase, Bbase, 32u);
        MMAF(fa0, fb0);
        // ks1: load ks2 -> buf0, mma buf1
        LOADF(fa0, fb0, Abase, Bbase, 64u);
        MMAF(fa1, fb1);
        // ks2: load ks3 -> buf1; all reads of stage st now issued
        LOADF(fa1, fb1, Abase, Bbase, 96u);
        __syncwarp();
        if (lid == 0) MBAR_ARRIVE(sb + 32 + st * 8);
        MMAF(fa0, fb0);
        // ks3: peek next stage, preload its ks0 -> buf0 under last burst
        if (kt + 1 < ktiles) {
            MBAR_WAIT(sb + stn * 8, phn);
            const uint32_t Ab2 = sb + CTRL + stn * STAGE_BYTES;
            const uint32_t Bb2 = Ab2 + TILE_B;
            LOADF(fa0, fb0, Ab2, Bb2, 0u);
        }
        MMAF(fa1, fb1);

        st = stn; ph = phn;
    }

    // ---- epilogue: h = f16(acc); h += f16(bias); out = f32(h) ----
    const int lr  = lid >> 2;
    const int lc2 = (lid & 3) * 2;
#pragma unroll
    for (int mti = 0; mti < 4; mti++) {
        const int row0 = m0 + wm + mti * 16 + lr;
        const int row1 = row0 + 8;
#pragma unroll
        for (int nti = 0; nti < 8; nti++) {
            const int col = n0 + wn + nti * 8 + lc2;
            const float2 bv = *(const float2*)&bias[col];
            const __half bh0 = __float2half_rn(bv.x);
            const __half bh1 = __float2half_rn(bv.y);

            __half h00 = __hadd(__float2half_rn(acc[mti][nti][0]), bh0);
            __half h01 = __hadd(__float2half_rn(acc[mti][nti][1]), bh1);
            __half h10 = __hadd(__float2half_rn(acc[mti][nti][2]), bh0);
            __half h11 = __hadd(__float2half_rn(acc[mti][nti][3]), bh1);

            *(float2*)&out[(size_t)row0 * N + col] =
                make_float2(__half2float(h00), __half2float(h01));
            *(float2*)&out[(size_t)row1 * N + col] =
                make_float2(__half2float(h10), __half2float(h11));
        }
    }
}

// ------------------------- launcher --------------------------------
extern "C" void kernel_launch(void* const* d_in, const int* in_sizes, int n_in,
                              void* d_out, int out_size)
{
    const float* x     = (const float*)d_in[0];
    const int*   wq    = (const int*)d_in[1];
    const float* scale = (const float*)d_in[2];
    const float* bias  = (const float*)d_in[3];
    float*       out   = (float*)d_out;

    const int N = in_sizes[3];              // 11008
    const int K = in_sizes[1] / N;          // 4096
    const int M = in_sizes[0] / K;          // 2048

    const int ktiles = K / 64;
    const long wgroups = (long)(N / 128) * ktiles * 1024;
    const long xgroups = (long)(M / 128) * ktiles * 1024;

    static int smem_set = 0;
    if (!smem_set) {
        cudaFuncSetAttribute(qgemm, cudaFuncAttributeMaxDynamicSharedMemorySize, GEMM_SMEM);
        smem_set = 1;
    }

    prep_w<<<(unsigned)((wgroups + 255) / 256), 256>>>(wq, scale, K, wgroups);
    prep_x<<<(unsigned)((xgroups + 255) / 256), 256>>>(x, K, xgroups);
    dim3 grid(M / 128, N / 128);            // M fastest: W stays L2-resident
    qgemm<<<grid, NTHREADS_G, GEMM_SMEM>>>(bias, out, M, N, K);
}

// round 11
// speedup vs baseline: 2.7469x; 2.7469x over previous
#include <cuda_runtime.h>
#include <cuda_fp16.h>
#include <stdint.h>

// ===================================================================
// Fused int8-dequant linear (sm_103 base ISA: no tcgen05).
//   out[m][n] = f32( f16( sum_k f16(x[m][k]) * (f16(wq[n][k])*f16(scale[n])) ) + f16(bias[n]) )
// Harness dtypes: x f32, weight_q i32, scale f32, bias f32, out f32.
// M=2048, N=11008, K=4096.
//
// Stage 1: ONE merged prep kernel: dequant W -> f16 and convert x -> f16
//   into __device__ scratch, 16KB SW128-swizzled tiles [128 x 64 halves].
// Stage 2: GEMM, CTA 128x128, BK=64, 5-stage cp.async.bulk ring,
//   4 compute warps (2x2, 64x64) + 1 producer, occ=1 (255-reg budget).
//   Fragment DOUBLE BUFFERING (no spills at occ1): LDSMs for step i+1
//   issued under the 32-HMMA burst of step i; early empty-arrive;
//   next-stage ks0 frags peek-loaded under the final burst.
// ===================================================================

#define NTILE_MAX 86
#define MTILE_MAX 16
#define KTILES_MAX 64

__device__ __half g_wf16[(size_t)NTILE_MAX * KTILES_MAX * 8192];
__device__ __half g_xf16[(size_t)MTILE_MAX * KTILES_MAX * 8192];

// ------------------------- PTX helpers -----------------------------
__device__ __forceinline__ uint32_t smem_u32(const void* p) {
    uint32_t a;
    asm("{ .reg .u64 t; cvta.to.shared.u64 t, %1; cvt.u32.u64 %0, t; }" : "=r"(a) : "l"(p));
    return a;
}

#define MBAR_INIT(addr, cnt) \
    asm volatile("mbarrier.init.shared.b64 [%0], %1;" :: "r"(addr), "r"(cnt) : "memory")

#define MBAR_EXPECT_TX(addr, bytes) \
    asm volatile("mbarrier.arrive.expect_tx.shared.b64 _, [%0], %1;" :: "r"(addr), "r"(bytes) : "memory")

#define MBAR_ARRIVE(addr) \
    asm volatile("mbarrier.arrive.release.cta.shared.b64 _, [%0];" :: "r"(addr) : "memory")

#define MBAR_WAIT(addr, ph) do {                                            \
    uint32_t _mb = (addr); uint32_t _p = (ph); uint32_t _done;              \
    asm volatile("{\n\t.reg .pred p;\n\t"                                   \
        "mbarrier.try_wait.parity.acquire.cta.shared::cta.b64 p, [%1], %2;\n\t" \
        "selp.b32 %0, 1, 0, p;\n\t}"                                        \
        : "=r"(_done) : "r"(_mb), "r"(_p) : "memory");                      \
    if (!_done) {                                                           \
        asm volatile("{\n\t.reg .pred P1;\n\t"                              \
            "WL_%=:\n\t"                                                    \
            "mbarrier.try_wait.parity.acquire.cta.shared::cta.b64 P1, [%0], %1, 0x989680;\n\t" \
            "@P1 bra.uni WD_%=;\n\t"                                        \
            "bra.uni WL_%=;\n\t"                                            \
            "WD_%=:\n\t}" :: "r"(_mb), "r"(_p) : "memory");                 \
    }                                                                       \
} while (0)

__device__ __forceinline__ void bulk_g2s(uint32_t dst, const void* src, uint32_t bytes, uint32_t mbar) {
    asm volatile(
        "cp.async.bulk.shared::cta.global.mbarrier::complete_tx::bytes [%0], [%1], %2, [%3];"
        :: "r"(dst), "l"(src), "r"(bytes), "r"(mbar) : "memory");
}

__device__ __forceinline__ void ldsm_x4(uint32_t r[4], uint32_t addr) {
    asm volatile("ldmatrix.sync.aligned.m8n8.x4.shared.b16 {%0,%1,%2,%3}, [%4];"
        : "=r"(r[0]), "=r"(r[1]), "=r"(r[2]), "=r"(r[3]) : "r"(addr));
}

__device__ __forceinline__ void mma16816(float d[4], const uint32_t a[4], const uint32_t b[2]) {
    asm volatile(
        "mma.sync.aligned.m16n8k16.row.col.f32.f16.f16.f32 "
        "{%0,%1,%2,%3}, {%4,%5,%6,%7}, {%8,%9}, {%0,%1,%2,%3};\n"
        : "+f"(d[0]), "+f"(d[1]), "+f"(d[2]), "+f"(d[3])
        : "r"(a[0]), "r"(a[1]), "r"(a[2]), "r"(a[3]), "r"(b[0]), "r"(b[1]));
}

__device__ __forceinline__ uint32_t sw128(uint32_t byte_off) {
    return byte_off ^ ((byte_off >> 3) & 0x70);
}

// ------------------------- merged prep kernel ----------------------
// idx < wgroups: weight dequant; else x convert. One uint4 per thread.
__global__ __launch_bounds__(256)
void prep_all(const int* __restrict__ wq, const float* __restrict__ scale,
              const float* __restrict__ x, int K, long wgroups, long total)
{
    long idx = (long)blockIdx.x * blockDim.x + threadIdx.x;
    if (idx >= total) return;
    const int ktiles = K >> 6;
    if (idx < wgroups) {
        int grp = (int)(idx & 1023);
        long blk = idx >> 10;
        int k_tile = (int)(blk % ktiles);
        int n_tile = (int)(blk / ktiles);
        int r  = grp >> 3;
        int c8 = grp & 7;
        int n = n_tile * 128 + r;
        int k = k_tile * 64 + c8 * 8;

        const int4* p = (const int4*)(wq + (size_t)n * K + k);
        int4 w0 = p[0], w1 = p[1];
        __half s = __float2half_rn(scale[n]);
        __half h[8];
        h[0] = __hmul(__int2half_rn(w0.x), s);
        h[1] = __hmul(__int2half_rn(w0.y), s);
        h[2] = __hmul(__int2half_rn(w0.z), s);
        h[3] = __hmul(__int2half_rn(w0.w), s);
        h[4] = __hmul(__int2half_rn(w1.x), s);
        h[5] = __hmul(__int2half_rn(w1.y), s);
        h[6] = __hmul(__int2half_rn(w1.z), s);
        h[7] = __hmul(__int2half_rn(w1.w), s);

        uint32_t off = sw128((uint32_t)(r * 128 + c8 * 16));
        *(uint4*)((char*)g_wf16 + blk * 16384 + off) = *(uint4*)h;
    } else {
        long xi = idx - wgroups;
        int grp = (int)(xi & 1023);
        long blk = xi >> 10;
        int k_tile = (int)(blk % ktiles);
        int m_tile = (int)(blk / ktiles);
        int r  = grp >> 3;
        int c8 = grp & 7;
        int m = m_tile * 128 + r;
        int k = k_tile * 64 + c8 * 8;

        const float4* p = (const float4*)(x + (size_t)m * K + k);
        float4 f0 = p[0], f1 = p[1];
        __half h[8];
        h[0] = __float2half_rn(f0.x); h[1] = __float2half_rn(f0.y);
        h[2] = __float2half_rn(f0.z); h[3] = __float2half_rn(f0.w);
        h[4] = __float2half_rn(f1.x); h[5] = __float2half_rn(f1.y);
        h[6] = __float2half_rn(f1.z); h[7] = __float2half_rn(f1.w);

        uint32_t off = sw128((uint32_t)(r * 128 + c8 * 16));
        *(uint4*)((char*)g_xf16 + blk * 16384 + off) = *(uint4*)h;
    }
}

// ------------------------- GEMM kernel -----------------------------
#define NSTAGES 5
#define TILE_B 16384
#define STAGE_BYTES (2 * TILE_B)
#define CTRL 1024
#define GEMM_SMEM (CTRL + NSTAGES * STAGE_BYTES)   // 164864 -> 1 CTA/SM
#define NTHREADS_G 160                 // 5 warps

__global__ __launch_bounds__(NTHREADS_G, 1)
void qgemm(const float* __restrict__ bias, float* __restrict__ out,
           int M, int N, int K)
{
    extern __shared__ __align__(1024) char smem[];
    const uint32_t sb = smem_u32(smem);
    const int tid  = threadIdx.x;
    const int lid  = tid & 31;
    const int warp = tid >> 5;

    const int mt_idx = blockIdx.x;         // M tile (fastest -> W L2 reuse)
    const int nt_idx = blockIdx.y;         // N tile
    const int ktiles = K >> 6;
    const int m0 = mt_idx * 128;
    const int n0 = nt_idx * 128;

    if (tid == 0) {
        for (int s = 0; s < NSTAGES; s++) {
            MBAR_INIT(sb + s * 8, 1);            // full
            MBAR_INIT(sb + 64 + s * 8, 4);       // empty
        }
    }
    __syncthreads();

    // ---------------- producer warp ----------------
    if (warp == 4) {
        if (lid == 0) {
            const char* Ag = (const char*)g_xf16 + (size_t)mt_idx * ktiles * TILE_B;
            const char* Bg = (const char*)g_wf16 + (size_t)nt_idx * ktiles * TILE_B;
            int st = 0, php = 1;
            for (int j = 0; j < ktiles; j++) {
                MBAR_WAIT(sb + 64 + st * 8, php);
                const uint32_t mbar = sb + st * 8;
                const uint32_t dst  = sb + CTRL + st * STAGE_BYTES;
                MBAR_EXPECT_TX(mbar, STAGE_BYTES);
                bulk_g2s(dst,          Ag + (size_t)j * TILE_B, TILE_B, mbar);
                bulk_g2s(dst + TILE_B, Bg + (size_t)j * TILE_B, TILE_B, mbar);
                if (++st == NSTAGES) { st = 0; php ^= 1; }
            }
        }
        return;
    }

    // ---------------- compute warps (2x2, warp tile 64x64) ----------------
    const int wm = (warp >> 1) * 64;
    const int wn = (warp & 1) * 64;

    const int ra       = lid & 15;
    const uint32_t swa = (uint32_t)(ra & 7) << 4;
    const uint32_t csa = (uint32_t)(lid >> 4) << 4;
    const int rb       = (lid & 7) + ((lid >> 4) << 3);
    const uint32_t swb = (uint32_t)(rb & 7) << 4;
    const uint32_t csb = (uint32_t)((lid >> 3) & 1) << 4;

    float acc[4][8][4];
#pragma unroll
    for (int i = 0; i < 4; i++)
#pragma unroll
        for (int j = 0; j < 8; j++)
#pragma unroll
            for (int c = 0; c < 4; c++) acc[i][j][c] = 0.f;

    // two fragment buffers (fits in 255-reg budget at occ 1)
    uint32_t fa0[4][4], fb0[8][2];
    uint32_t fa1[4][4], fb1[8][2];

#define LOADF(FA, FB, ABASE, BBASE, KB) do {                                  \
    _Pragma("unroll")                                                         \
    for (int _mt = 0; _mt < 4; _mt++) {                                       \
        const int _r = wm + _mt * 16 + ra;                                    \
        ldsm_x4(FA[_mt], (ABASE) + (uint32_t)_r * 128 + (((KB) + csa) ^ swa));\
    }                                                                         \
    _Pragma("unroll")                                                         \
    for (int _q = 0; _q < 4; _q++) {                                          \
        const int _n = wn + _q * 16 + rb;                                     \
        uint32_t _t[4];                                                       \
        ldsm_x4(_t, (BBASE) + (uint32_t)_n * 128 + (((KB) + csb) ^ swb));     \
        FB[2*_q][0] = _t[0]; FB[2*_q][1] = _t[1];                             \
        FB[2*_q+1][0] = _t[2]; FB[2*_q+1][1] = _t[3];                         \
    }                                                                         \
} while (0)

#define MMAF(FA, FB) do {                                                     \
    _Pragma("unroll")                                                         \
    for (int _mt = 0; _mt < 4; _mt++)                                         \
        _Pragma("unroll")                                                     \
        for (int _nt = 0; _nt < 8; _nt++)                                     \
            mma16816(acc[_mt][_nt], FA[_mt], FB[_nt]);                        \
} while (0)

    int st = 0, ph = 0;
    // prologue: wait stage 0, load ks0 into buf0
    MBAR_WAIT(sb + 0, 0);
    {
        const uint32_t Ab = sb + CTRL;
        const uint32_t Bb = Ab + TILE_B;
        LOADF(fa0, fb0, Ab, Bb, 0u);
    }

    for (int kt = 0; kt < ktiles; kt++) {
        const uint32_t Abase = sb + CTRL + st * STAGE_BYTES;
        const uint32_t Bbase = Abase + TILE_B;
        const int stn = (st + 1 == NSTAGES) ? 0 : st + 1;
        const int phn = (st + 1 == NSTAGES) ? (ph ^ 1) : ph;

        // ks0: load ks1 -> buf1, mma buf0
        LOADF(fa1, fb1, Abase, Bbase, 32u);
        MMAF(fa0, fb0);
        // ks1: load ks2 -> buf0, mma buf1
        LOADF(fa0, fb0, Abase, Bbase, 64u);
        MMAF(fa1, fb1);
        // ks2: load ks3 -> buf1; all reads of stage st now issued
        LOADF(fa1, fb1, Abase, Bbase, 96u);
        __syncwarp();
        if (lid == 0) MBAR_ARRIVE(sb + 64 + st * 8);
        MMAF(fa0, fb0);
        // ks3: peek next stage, preload its ks0 -> buf0 under last burst
        if (kt + 1 < ktiles) {
            MBAR_WAIT(sb + stn * 8, phn);
            const uint32_t Ab2 = sb + CTRL + stn * STAGE_BYTES;
            const uint32_t Bb2 = Ab2 + TILE_B;
            LOADF(fa0, fb0, Ab2, Bb2, 0u);
        }
        MMAF(fa1, fb1);

        st = stn; ph = phn;
    }

    // ---- epilogue: h = f16(acc); h += f16(bias); out = f32(h) ----
    const int lr  = lid >> 2;
    const int lc2 = (lid & 3) * 2;
#pragma unroll
    for (int mti = 0; mti < 4; mti++) {
        const int row0 = m0 + wm + mti * 16 + lr;
        const int row1 = row0 + 8;
#pragma unroll
        for (int nti = 0; nti < 8; nti++) {
            const int col = n0 + wn + nti * 8 + lc2;
            const float2 bv = *(const float2*)&bias[col];
            const __half bh0 = __float2half_rn(bv.x);
            const __half bh1 = __float2half_rn(bv.y);

            __half h00 = __hadd(__float2half_rn(acc[mti][nti][0]), bh0);
            __half h01 = __hadd(__float2half_rn(acc[mti][nti][1]), bh1);
            __half h10 = __hadd(__float2half_rn(acc[mti][nti][2]), bh0);
            __half h11 = __hadd(__float2half_rn(acc[mti][nti][3]), bh1);

            *(float2*)&out[(size_t)row0 * N + col] =
                make_float2(__half2float(h00), __half2float(h01));
            *(float2*)&out[(size_t)row1 * N + col] =
                make_float2(__half2float(h10), __half2float(h11));
        }
    }
}

// ------------------------- launcher --------------------------------
extern "C" void kernel_launch(void* const* d_in, const int* in_sizes, int n_in,
                              void* d_out, int out_size)
{
    const float* x     = (const float*)d_in[0];
    const int*   wq    = (const int*)d_in[1];
    const float* scale = (const float*)d_in[2];
    const float* bias  = (const float*)d_in[3];
    float*       out   = (float*)d_out;

    const int N = in_sizes[3];              // 11008
    const int K = in_sizes[1] / N;          // 4096
    const int M = in_sizes[0] / K;          // 2048

    const int ktiles = K / 64;
    const long wgroups = (long)(N / 128) * ktiles * 1024;
    const long xgroups = (long)(M / 128) * ktiles * 1024;
    const long total   = wgroups + xgroups;

    static int smem_set = 0;
    if (!smem_set) {
        cudaFuncSetAttribute(qgemm, cudaFuncAttributeMaxDynamicSharedMemorySize, GEMM_SMEM);
        smem_set = 1;
    }

    prep_all<<<(unsigned)((total + 255) / 256), 256>>>(wq, scale, x, K, wgroups, total);
    dim3 grid(M / 128, N / 128);            // M fastest: W stays L2-resident
    qgemm<<<grid, NTHREADS_G, GEMM_SMEM>>>(bias, out, M, N, K);
}

// round 12
// speedup vs baseline: 3.0304x; 1.1032x over previous
#include <cuda_runtime.h>
#include <cuda_fp16.h>
#include <stdint.h>

// ===================================================================
// Fused int8-dequant linear (sm_103 base ISA: no tcgen05).
//   out[m][n] = f32( f16( sum_k f16(x[m][k]) * (f16(wq[n][k])*f16(scale[n])) ) + f16(bias[n]) )
// Harness dtypes: x f32, weight_q i32, scale f32, bias f32, out f32.
// M=2048, N=11008, K=4096.
//
// Stage 1: merged prep kernel: W -> f16*scale, x -> f16, into scratch,
//   16KB SW128-swizzled tiles [128 rows x 64 halves].
// Stage 2: GEMM, CTA 128x128, BK=64, 5-stage cp.async.bulk ring.
//   8 compute warps (2x4, warp tile 64x32 -> 2 warps/SMSP for latency
//   interleave) + 1 producer. Fragment double buffering (~150 regs, no
//   spill). Early empty-arrive; next-stage frags peek-loaded under the
//   final HMMA burst.
// ===================================================================

#define NTILE_MAX 86
#define MTILE_MAX 16
#define KTILES_MAX 64

__device__ __half g_wf16[(size_t)NTILE_MAX * KTILES_MAX * 8192];
__device__ __half g_xf16[(size_t)MTILE_MAX * KTILES_MAX * 8192];

// ------------------------- PTX helpers -----------------------------
__device__ __forceinline__ uint32_t smem_u32(const void* p) {
    uint32_t a;
    asm("{ .reg .u64 t; cvta.to.shared.u64 t, %1; cvt.u32.u64 %0, t; }" : "=r"(a) : "l"(p));
    return a;
}

#define MBAR_INIT(addr, cnt) \
    asm volatile("mbarrier.init.shared.b64 [%0], %1;" :: "r"(addr), "r"(cnt) : "memory")

#define MBAR_EXPECT_TX(addr, bytes) \
    asm volatile("mbarrier.arrive.expect_tx.shared.b64 _, [%0], %1;" :: "r"(addr), "r"(bytes) : "memory")

#define MBAR_ARRIVE(addr) \
    asm volatile("mbarrier.arrive.release.cta.shared.b64 _, [%0];" :: "r"(addr) : "memory")

#define MBAR_WAIT(addr, ph) do {                                            \
    uint32_t _mb = (addr); uint32_t _p = (ph); uint32_t _done;              \
    asm volatile("{\n\t.reg .pred p;\n\t"                                   \
        "mbarrier.try_wait.parity.acquire.cta.shared::cta.b64 p, [%1], %2;\n\t" \
        "selp.b32 %0, 1, 0, p;\n\t}"                                        \
        : "=r"(_done) : "r"(_mb), "r"(_p) : "memory");                      \
    if (!_done) {                                                           \
        asm volatile("{\n\t.reg .pred P1;\n\t"                              \
            "WL_%=:\n\t"                                                    \
            "mbarrier.try_wait.parity.acquire.cta.shared::cta.b64 P1, [%0], %1, 0x989680;\n\t" \
            "@P1 bra.uni WD_%=;\n\t"                                        \
            "bra.uni WL_%=;\n\t"                                            \
            "WD_%=:\n\t}" :: "r"(_mb), "r"(_p) : "memory");                 \
    }                                                                       \
} while (0)

__device__ __forceinline__ void bulk_g2s(uint32_t dst, const void* src, uint32_t bytes, uint32_t mbar) {
    asm volatile(
        "cp.async.bulk.shared::cta.global.mbarrier::complete_tx::bytes [%0], [%1], %2, [%3];"
        :: "r"(dst), "l"(src), "r"(bytes), "r"(mbar) : "memory");
}

__device__ __forceinline__ void ldsm_x4(uint32_t r[4], uint32_t addr) {
    asm volatile("ldmatrix.sync.aligned.m8n8.x4.shared.b16 {%0,%1,%2,%3}, [%4];"
        : "=r"(r[0]), "=r"(r[1]), "=r"(r[2]), "=r"(r[3]) : "r"(addr));
}

__device__ __forceinline__ void mma16816(float d[4], const uint32_t a[4], const uint32_t b[2]) {
    asm volatile(
        "mma.sync.aligned.m16n8k16.row.col.f32.f16.f16.f32 "
        "{%0,%1,%2,%3}, {%4,%5,%6,%7}, {%8,%9}, {%0,%1,%2,%3};\n"
        : "+f"(d[0]), "+f"(d[1]), "+f"(d[2]), "+f"(d[3])
        : "r"(a[0]), "r"(a[1]), "r"(a[2]), "r"(a[3]), "r"(b[0]), "r"(b[1]));
}

__device__ __forceinline__ uint32_t sw128(uint32_t byte_off) {
    return byte_off ^ ((byte_off >> 3) & 0x70);
}

// ------------------------- merged prep kernel ----------------------
__global__ __launch_bounds__(256)
void prep_all(const int* __restrict__ wq, const float* __restrict__ scale,
              const float* __restrict__ x, int K, long wgroups, long total)
{
    long idx = (long)blockIdx.x * blockDim.x + threadIdx.x;
    if (idx >= total) return;
    const int ktiles = K >> 6;
    if (idx < wgroups) {
        int grp = (int)(idx & 1023);
        long blk = idx >> 10;
        int k_tile = (int)(blk % ktiles);
        int n_tile = (int)(blk / ktiles);
        int r  = grp >> 3;
        int c8 = grp & 7;
        int n = n_tile * 128 + r;
        int k = k_tile * 64 + c8 * 8;

        const int4* p = (const int4*)(wq + (size_t)n * K + k);
        int4 w0 = p[0], w1 = p[1];
        __half s = __float2half_rn(scale[n]);
        __half h[8];
        h[0] = __hmul(__int2half_rn(w0.x), s);
        h[1] = __hmul(__int2half_rn(w0.y), s);
        h[2] = __hmul(__int2half_rn(w0.z), s);
        h[3] = __hmul(__int2half_rn(w0.w), s);
        h[4] = __hmul(__int2half_rn(w1.x), s);
        h[5] = __hmul(__int2half_rn(w1.y), s);
        h[6] = __hmul(__int2half_rn(w1.z), s);
        h[7] = __hmul(__int2half_rn(w1.w), s);

        uint32_t off = sw128((uint32_t)(r * 128 + c8 * 16));
        *(uint4*)((char*)g_wf16 + blk * 16384 + off) = *(uint4*)h;
    } else {
        long xi = idx - wgroups;
        int grp = (int)(xi & 1023);
        long blk = xi >> 10;
        int k_tile = (int)(blk % ktiles);
        int m_tile = (int)(blk / ktiles);
        int r  = grp >> 3;
        int c8 = grp & 7;
        int m = m_tile * 128 + r;
        int k = k_tile * 64 + c8 * 8;

        const float4* p = (const float4*)(x + (size_t)m * K + k);
        float4 f0 = p[0], f1 = p[1];
        __half h[8];
        h[0] = __float2half_rn(f0.x); h[1] = __float2half_rn(f0.y);
        h[2] = __float2half_rn(f0.z); h[3] = __float2half_rn(f0.w);
        h[4] = __float2half_rn(f1.x); h[5] = __float2half_rn(f1.y);
        h[6] = __float2half_rn(f1.z); h[7] = __float2half_rn(f1.w);

        uint32_t off = sw128((uint32_t)(r * 128 + c8 * 16));
        *(uint4*)((char*)g_xf16 + blk * 16384 + off) = *(uint4*)h;
    }
}

// ------------------------- GEMM kernel -----------------------------
#define NSTAGES 5
#define TILE_B 16384
#define STAGE_BYTES (2 * TILE_B)
#define CTRL 1024
#define GEMM_SMEM (CTRL + NSTAGES * STAGE_BYTES)   // 164864 -> 1 CTA/SM
#define NTHREADS_G 288                 // 9 warps: 8 compute + 1 producer

__global__ __launch_bounds__(NTHREADS_G, 1)
void qgemm(const float* __restrict__ bias, float* __restrict__ out,
           int M, int N, int K)
{
    extern __shared__ __align__(1024) char smem[];
    const uint32_t sb = smem_u32(smem);
    const int tid  = threadIdx.x;
    const int lid  = tid & 31;
    const int warp = tid >> 5;

    const int mt_idx = blockIdx.x;         // M tile (fastest -> W L2 reuse)
    const int nt_idx = blockIdx.y;         // N tile
    const int ktiles = K >> 6;
    const int m0 = mt_idx * 128;
    const int n0 = nt_idx * 128;

    if (tid == 0) {
        for (int s = 0; s < NSTAGES; s++) {
            MBAR_INIT(sb + s * 8, 1);            // full
            MBAR_INIT(sb + 64 + s * 8, 8);       // empty: 8 compute warps
        }
    }
    __syncthreads();

    // ---------------- producer warp ----------------
    if (warp == 8) {
        if (lid == 0) {
            const char* Ag = (const char*)g_xf16 + (size_t)mt_idx * ktiles * TILE_B;
            const char* Bg = (const char*)g_wf16 + (size_t)nt_idx * ktiles * TILE_B;
            int st = 0, php = 1;
            for (int j = 0; j < ktiles; j++) {
                MBAR_WAIT(sb + 64 + st * 8, php);
                const uint32_t mbar = sb + st * 8;
                const uint32_t dst  = sb + CTRL + st * STAGE_BYTES;
                MBAR_EXPECT_TX(mbar, STAGE_BYTES);
                bulk_g2s(dst,          Ag + (size_t)j * TILE_B, TILE_B, mbar);
                bulk_g2s(dst + TILE_B, Bg + (size_t)j * TILE_B, TILE_B, mbar);
                if (++st == NSTAGES) { st = 0; php ^= 1; }
            }
        }
        return;
    }

    // -------- compute warps: 2 (M) x 4 (N), warp tile 64x32 --------
    const int wm = (warp >> 2) * 64;     // 0,64
    const int wn = (warp & 3) * 32;      // 0,32,64,96

    const int ra       = lid & 15;
    const uint32_t swa = (uint32_t)(ra & 7) << 4;
    const uint32_t csa = (uint32_t)(lid >> 4) << 4;
    const int rb       = (lid & 7) + ((lid >> 4) << 3);
    const uint32_t swb = (uint32_t)(rb & 7) << 4;
    const uint32_t csb = (uint32_t)((lid >> 3) & 1) << 4;

    float acc[4][4][4];
#pragma unroll
    for (int i = 0; i < 4; i++)
#pragma unroll
        for (int j = 0; j < 4; j++)
#pragma unroll
            for (int c = 0; c < 4; c++) acc[i][j][c] = 0.f;

    // two fragment buffers: A 16+16, B 8+8 regs
    uint32_t fa0[4][4], fb0[4][2];
    uint32_t fa1[4][4], fb1[4][2];

#define LOADF(FA, FB, ABASE, BBASE, KB) do {                                  \
    _Pragma("unroll")                                                         \
    for (int _mt = 0; _mt < 4; _mt++) {                                       \
        const int _r = wm + _mt * 16 + ra;                                    \
        ldsm_x4(FA[_mt], (ABASE) + (uint32_t)_r * 128 + (((KB) + csa) ^ swa));\
    }                                                                         \
    _Pragma("unroll")                                                         \
    for (int _q = 0; _q < 2; _q++) {                                          \
        const int _n = wn + _q * 16 + rb;                                     \
        uint32_t _t[4];                                                       \
        ldsm_x4(_t, (BBASE) + (uint32_t)_n * 128 + (((KB) + csb) ^ swb));     \
        FB[2*_q][0] = _t[0]; FB[2*_q][1] = _t[1];                             \
        FB[2*_q+1][0] = _t[2]; FB[2*_q+1][1] = _t[3];                         \
    }                                                                         \
} while (0)

#define MMAF(FA, FB) do {                                                     \
    _Pragma("unroll")                                                         \
    for (int _mt = 0; _mt < 4; _mt++)                                         \
        _Pragma("unroll")                                                     \
        for (int _nt = 0; _nt < 4; _nt++)                                     \
            mma16816(acc[_mt][_nt], FA[_mt], FB[_nt]);                        \
} while (0)

    int st = 0, ph = 0;
    // prologue: wait stage 0, load ks0 into buf0
    MBAR_WAIT(sb + 0, 0);
    {
        const uint32_t Ab = sb + CTRL;
        const uint32_t Bb = Ab + TILE_B;
        LOADF(fa0, fb0, Ab, Bb, 0u);
    }

    for (int kt = 0; kt < ktiles; kt++) {
        const uint32_t Abase = sb + CTRL + st * STAGE_BYTES;
        const uint32_t Bbase = Abase + TILE_B;
        const int stn = (st + 1 == NSTAGES) ? 0 : st + 1;
        const int phn = (st + 1 == NSTAGES) ? (ph ^ 1) : ph;

        // ks0: load ks1 -> buf1, mma buf0
        LOADF(fa1, fb1, Abase, Bbase, 32u);
        MMAF(fa0, fb0);
        // ks1: load ks2 -> buf0, mma buf1
        LOADF(fa0, fb0, Abase, Bbase, 64u);
        MMAF(fa1, fb1);
        // ks2: load ks3 -> buf1; all reads of stage st now issued
        LOADF(fa1, fb1, Abase, Bbase, 96u);
        __syncwarp();
        if (lid == 0) MBAR_ARRIVE(sb + 64 + st * 8);
        MMAF(fa0, fb0);
        // ks3: peek next stage, preload its ks0 -> buf0 under last burst
        if (kt + 1 < ktiles) {
            MBAR_WAIT(sb + stn * 8, phn);
            const uint32_t Ab2 = sb + CTRL + stn * STAGE_BYTES;
            const uint32_t Bb2 = Ab2 + TILE_B;
            LOADF(fa0, fb0, Ab2, Bb2, 0u);
        }
        MMAF(fa1, fb1);

        st = stn; ph = phn;
    }

    // ---- epilogue: h = f16(acc); h += f16(bias); out = f32(h) ----
    const int lr  = lid >> 2;
    const int lc2 = (lid & 3) * 2;
#pragma unroll
    for (int mti = 0; mti < 4; mti++) {
        const int row0 = m0 + wm + mti * 16 + lr;
        const int row1 = row0 + 8;
#pragma unroll
        for (int nti = 0; nti < 4; nti++) {
            const int col = n0 + wn + nti * 8 + lc2;
            const float2 bv = *(const float2*)&bias[col];
            const __half bh0 = __float2half_rn(bv.x);
            const __half bh1 = __float2half_rn(bv.y);

            __half h00 = __hadd(__float2half_rn(acc[mti][nti][0]), bh0);
            __half h01 = __hadd(__float2half_rn(acc[mti][nti][1]), bh1);
            __half h10 = __hadd(__float2half_rn(acc[mti][nti][2]), bh0);
            __half h11 = __hadd(__float2half_rn(acc[mti][nti][3]), bh1);

            *(float2*)&out[(size_t)row0 * N + col] =
                make_float2(__half2float(h00), __half2float(h01));
            *(float2*)&out[(size_t)row1 * N + col] =
                make_float2(__half2float(h10), __half2float(h11));
        }
    }
}

// ------------------------- launcher --------------------------------
extern "C" void kernel_launch(void* const* d_in, const int* in_sizes, int n_in,
                              void* d_out, int out_size)
{
    const float* x     = (const float*)d_in[0];
    const int*   wq    = (const int*)d_in[1];
    const float* scale = (const float*)d_in[2];
    const float* bias  = (const float*)d_in[3];
    float*       out   = (float*)d_out;

    const int N = in_sizes[3];              // 11008
    const int K = in_sizes[1] / N;          // 4096
    const int M = in_sizes[0] / K;          // 2048

    const int ktiles = K / 64;
    const long wgroups = (long)(N / 128) * ktiles * 1024;
    const long xgroups = (long)(M / 128) * ktiles * 1024;
    const long total   = wgroups + xgroups;

    static int smem_set = 0;
    if (!smem_set) {
        cudaFuncSetAttribute(qgemm, cudaFuncAttributeMaxDynamicSharedMemorySize, GEMM_SMEM);
        smem_set = 1;
    }

    prep_all<<<(unsigned)((total + 255) / 256), 256>>>(wq, scale, x, K, wgroups, total);
    dim3 grid(M / 128, N / 128);            // M fastest: W stays L2-resident
    qgemm<<<grid, NTHREADS_G, GEMM_SMEM>>>(bias, out, M, N, K);
}